// round 1
// baseline (speedup 1.0000x reference)
#include <cuda_runtime.h>

#define T_FRAMES 32768
#define N_LM 543
#define NLEN 512
#define NCOLS 122   // 21*2 hand + 40*2 lips
#define NHANDF 42
#define NLIPSF 80

// ---- device scratch (static; no allocations) ----
__device__ float g_raw[T_FRAMES * NCOLS];   // per-frame raw row (hand transformed+nan0, lips raw w/ NaN)
__device__ int   g_keep[T_FRAMES];
__device__ int   g_map[T_FRAMES];           // s -> t for kept frames, in order
__device__ float g_lsum[NLIPSF];
__device__ int   g_lcnt[NLIPSF];
__device__ float g_lmean[NLIPSF];
__device__ int   g_S;
__device__ float g_sampled[NLEN * NCOLS];
__device__ int   g_rowflag[NLEN];

__device__ __forceinline__ bool is_nan(float v) { return v != v; }

// ---- kernel 0: zero accumulators (must run every launch for graph replay) ----
__global__ void k_init() {
    int i = threadIdx.x;
    if (i < NLIPSF) { g_lsum[i] = 0.f; g_lcnt[i] = 0; }
}

// ---- kernel 1: per-frame hand transform + keep + raw buffer + lips accumulation ----
// one warp per frame; 256 threads/block = 8 frames/block
__global__ void k_frame(const float* __restrict__ frames, const int* __restrict__ lips_idx) {
    __shared__ float s_sum[NLIPSF];
    __shared__ int   s_cnt[NLIPSF];
    __shared__ int   s_lidx[40];

    int tib  = threadIdx.x;
    int lane = tib & 31;
    int t    = (blockIdx.x * blockDim.x + tib) >> 5;

    if (tib < NLIPSF) { s_sum[tib] = 0.f; s_cnt[tib] = 0; }
    if (tib < 40)     s_lidx[tib] = lips_idx[tib];
    __syncthreads();

    if (t < T_FRAMES) {
        const float* fb = frames + (size_t)t * (N_LM * 3);
        float h0 = 0.f, h1 = 0.f;
        if (lane < 21) {
            float lx = fb[(468 + lane) * 3 + 0];
            float ly = fb[(468 + lane) * 3 + 1];
            float rx = fb[(522 + lane) * 3 + 0];
            float ry = fb[(522 + lane) * 3 + 1];
            float a0 = is_nan(lx) ? 0.f : lx;
            float a1 = is_nan(ly) ? 0.f : (1.f - ly);
            float b0 = is_nan(rx) ? 0.f : (1.f - rx);
            float b1 = is_nan(ry) ? 0.f : (1.f - ry);
            h0 = a0 + b0;
            h1 = a1 + b1;
            g_raw[t * NCOLS + 2 * lane + 0] = h0;
            g_raw[t * NCOLS + 2 * lane + 1] = h1;
        }
        // keep = (sum of non-negative hand terms) != 0  (order-independent)
        float ps = h0 + h1;
        #pragma unroll
        for (int off = 16; off; off >>= 1)
            ps += __shfl_xor_sync(0xffffffffu, ps, off);
        int keep = (ps != 0.f);
        if (lane == 0) g_keep[t] = keep;

        // lips gather: 40 landmarks, 2 per lane (lanes 0..19 handle j and j+20)
        for (int j = lane; j < 40; j += 32) {
            int li  = s_lidx[j];
            float x = fb[li * 3 + 0];
            float y = fb[li * 3 + 1];
            g_raw[t * NCOLS + NHANDF + 2 * j + 0] = x;
            g_raw[t * NCOLS + NHANDF + 2 * j + 1] = y;
            if (keep) {
                if (!is_nan(x)) { atomicAdd(&s_sum[2 * j + 0], x); atomicAdd(&s_cnt[2 * j + 0], 1); }
                if (!is_nan(y)) { atomicAdd(&s_sum[2 * j + 1], y); atomicAdd(&s_cnt[2 * j + 1], 1); }
            }
        }
    }
    __syncthreads();
    if (tib < NLIPSF && s_cnt[tib]) {
        atomicAdd(&g_lsum[tib], s_sum[tib]);
        atomicAdd(&g_lcnt[tib], s_cnt[tib]);
    }
}

// ---- kernel 2: single-block scan of keep flags -> kept map + S; lips means ----
__global__ void k_scan() {
    int tid = threadIdx.x;   // 1024 threads
    if (tid < NLIPSF) {
        int c = g_lcnt[tid];
        g_lmean[tid] = (c > 0) ? g_lsum[tid] / (float)c : 0.f;
    }
    __shared__ int s[1024];
    int base = tid * 32;
    int local = 0;
    #pragma unroll
    for (int k = 0; k < 32; k++) local += g_keep[base + k];
    s[tid] = local;
    __syncthreads();
    for (int off = 1; off < 1024; off <<= 1) {
        int v = (tid >= off) ? s[tid - off] : 0;
        __syncthreads();
        s[tid] += v;
        __syncthreads();
    }
    int pos = s[tid] - local;  // exclusive prefix
    for (int k = 0; k < 32; k++) {
        int t = base + k;
        if (g_keep[t]) g_map[pos++] = t;
    }
    if (tid == 1023) g_S = s[1023];
}

// ---- kernel 3: segment means (512 blocks, thread = column) + row flags ----
__global__ void k_segment() {
    int i = blockIdx.x;
    int S = g_S;
    int lo = 0, hi = 0;
    if (S >= 2) {
        long sm1 = (long)(S - 1);
        lo = (int)(((long)i       * sm1) >> 9);   // floor(i*(S-1)/512)
        hi = (int)(((long)(i + 1) * sm1) >> 9);
    }
    int cnt = hi - lo;
    int j = threadIdx.x;   // 128 threads, 122 used
    float mean = 0.f;
    if (j < NCOLS) {
        float fill = (j >= NHANDF) ? g_lmean[j - NHANDF] : 0.f;
        float sum = 0.f;
        for (int s = lo; s < hi; s++) {
            int t = g_map[s];
            float v = g_raw[t * NCOLS + j];
            if (is_nan(v)) v = fill;
            sum += v;
        }
        mean = cnt ? sum / (float)cnt : 0.f;
        g_sampled[i * NCOLS + j] = mean;
    }
    __shared__ float red[128];
    red[threadIdx.x] = mean;
    __syncthreads();
    #pragma unroll
    for (int off = 64; off; off >>= 1) {
        if (threadIdx.x < off) red[threadIdx.x] += red[threadIdx.x + off];
        __syncthreads();
    }
    if (threadIdx.x == 0) g_rowflag[i] = (red[0] != 0.f);
}

// ---- kernel 4: row compaction into d_out ----
__global__ void k_compact(float* __restrict__ out, int out_size) {
    __shared__ int sflag[NLEN];
    __shared__ int ssrc[NLEN];
    int tid = threadIdx.x;   // 512 threads
    int f = g_rowflag[tid];
    sflag[tid] = f;
    __syncthreads();
    for (int off = 1; off < NLEN; off <<= 1) {
        int v = (tid >= off) ? sflag[tid - off] : 0;
        __syncthreads();
        sflag[tid] += v;
        __syncthreads();
    }
    if (f) ssrc[sflag[tid] - 1] = tid;
    __syncthreads();
    int R = sflag[NLEN - 1];
    int total = R * NCOLS;
    if (total > out_size) total = out_size;
    for (int k = tid; k < total; k += NLEN) {
        int r = k / NCOLS;
        int c = k - r * NCOLS;
        out[k] = g_sampled[ssrc[r] * NCOLS + c];
    }
}

extern "C" void kernel_launch(void* const* d_in, const int* in_sizes, int n_in,
                              void* d_out, int out_size) {
    const float* frames   = (const float*)d_in[0];
    const int*   lips_idx = (const int*)d_in[1];
    float*       out      = (float*)d_out;

    k_init<<<1, 128>>>();
    // one warp per frame: 32768 warps = 1,048,576 threads
    k_frame<<<(T_FRAMES * 32) / 256, 256>>>(frames, lips_idx);
    k_scan<<<1, 1024>>>();
    k_segment<<<NLEN, 128>>>();
    k_compact<<<1, NLEN>>>(out, out_size);
}

// round 2
// speedup vs baseline: 1.3899x; 1.3899x over previous
#include <cuda_runtime.h>

#define T_FRAMES 32768
#define N_LM 543
#define NLEN 512
#define NCOLS 122   // 21*2 hand + 40*2 lips
#define NHANDF 42
#define NLIPSF 80
#define FPB 8       // frames per block in k_frame (256 threads)

// ---- device scratch (static; no allocations) ----
__device__ float g_raw[T_FRAMES * NCOLS];
__device__ int   g_keep[T_FRAMES];
__device__ int   g_map[T_FRAMES];
__device__ float g_lsum[NLIPSF];
__device__ int   g_lcnt[NLIPSF];
__device__ float g_lmean[NLIPSF];
__device__ int   g_S;
__device__ float g_sampled[NLEN * NCOLS];
__device__ int   g_rowflag[NLEN];

__device__ __forceinline__ bool is_nan(float v) { return v != v; }

// ---- kernel 0: zero accumulators (must run every replay) ----
__global__ void k_init() {
    int i = threadIdx.x;
    if (i < NLIPSF) { g_lsum[i] = 0.f; g_lcnt[i] = 0; }
}

// ---- kernel 1: per-frame hand transform + keep + raw buffer + lips accumulation ----
// one warp per frame; FPB frames per 256-thread block; NO per-value atomics.
__global__ void k_frame(const float* __restrict__ frames, const int* __restrict__ lips_idx) {
    __shared__ int   s_lidx[40];
    __shared__ float s_lips[FPB][NLIPSF];

    int tib  = threadIdx.x;
    int lane = tib & 31;
    int w    = tib >> 5;
    int t    = blockIdx.x * FPB + w;
    const float NANF = __int_as_float(0x7fc00000);

    if (tib < 40) s_lidx[tib] = lips_idx[tib];
    __syncthreads();

    const float* fb = frames + (size_t)t * (N_LM * 3);

    float h0 = 0.f, h1 = 0.f;
    if (lane < 21) {
        float lx = fb[(468 + lane) * 3 + 0];
        float ly = fb[(468 + lane) * 3 + 1];
        float rx = fb[(522 + lane) * 3 + 0];
        float ry = fb[(522 + lane) * 3 + 1];
        float a0 = is_nan(lx) ? 0.f : lx;
        float a1 = is_nan(ly) ? 0.f : (1.f - ly);
        float b0 = is_nan(rx) ? 0.f : (1.f - rx);
        float b1 = is_nan(ry) ? 0.f : (1.f - ry);
        h0 = a0 + b0;
        h1 = a1 + b1;
        g_raw[t * NCOLS + 2 * lane + 0] = h0;
        g_raw[t * NCOLS + 2 * lane + 1] = h1;
    }
    // keep = (sum of non-negative hand terms) != 0  (order-independent)
    float ps = h0 + h1;
    #pragma unroll
    for (int off = 16; off; off >>= 1)
        ps += __shfl_xor_sync(0xffffffffu, ps, off);
    int keep = (ps != 0.f);
    if (lane == 0) g_keep[t] = keep;

    // lips gather; stash (value-if-kept-else-NaN) in shared for block reduction
    #pragma unroll
    for (int j = lane; j < 40; j += 32) {
        int li  = s_lidx[j];
        float x = fb[li * 3 + 0];
        float y = fb[li * 3 + 1];
        g_raw[t * NCOLS + NHANDF + 2 * j + 0] = x;
        g_raw[t * NCOLS + NHANDF + 2 * j + 1] = y;
        s_lips[w][2 * j + 0] = keep ? x : NANF;
        s_lips[w][2 * j + 1] = keep ? y : NANF;
    }
    __syncthreads();

    // 80 threads: reduce FPB frames for one column, single global atomic pair
    if (tib < NLIPSF) {
        float s = 0.f; int c = 0;
        #pragma unroll
        for (int f = 0; f < FPB; f++) {
            float v = s_lips[f][tib];
            if (!is_nan(v)) { s += v; c++; }
        }
        if (c) {
            atomicAdd(&g_lsum[tib], s);
            atomicAdd(&g_lcnt[tib], c);
        }
    }
}

// ---- kernel 2: single-block scan of keep flags -> kept map + S; lips means ----
__global__ void k_scan() {
    int tid = threadIdx.x;   // 1024 threads
    if (tid < NLIPSF) {
        int c = g_lcnt[tid];
        g_lmean[tid] = (c > 0) ? g_lsum[tid] / (float)c : 0.f;
    }
    __shared__ int s[1024];
    int base = tid * 32;
    int local = 0;
    #pragma unroll
    for (int k = 0; k < 32; k++) local += g_keep[base + k];
    s[tid] = local;
    __syncthreads();
    for (int off = 1; off < 1024; off <<= 1) {
        int v = (tid >= off) ? s[tid - off] : 0;
        __syncthreads();
        s[tid] += v;
        __syncthreads();
    }
    int pos = s[tid] - local;  // exclusive prefix
    for (int k = 0; k < 32; k++) {
        int t = base + k;
        if (g_keep[t]) g_map[pos++] = t;
    }
    if (tid == 1023) g_S = s[1023];
}

// ---- kernel 3: segment means (512 blocks x 256 thr, 2-way frame split) ----
__global__ void k_segment() {
    int i = blockIdx.x;
    int S = g_S;
    int lo = 0, hi = 0;
    if (S >= 2) {
        long sm1 = (long)(S - 1);
        lo = (int)(((long)i       * sm1) >> 9);   // floor(i*(S-1)/512)
        hi = (int)(((long)(i + 1) * sm1) >> 9);
    }
    int cnt  = hi - lo;
    int j    = threadIdx.x & 127;   // column
    int half = threadIdx.x >> 7;    // 0/1: even/odd frames of the segment

    float sum = 0.f;
    if (j < NCOLS) {
        float fill = (j >= NHANDF) ? g_lmean[j - NHANDF] : 0.f;
        #pragma unroll 4
        for (int s = lo + half; s < hi; s += 2) {
            int t = __ldg(&g_map[s]);
            float v = g_raw[t * NCOLS + j];
            sum += is_nan(v) ? fill : v;
        }
    }
    __shared__ float red2[128];
    if (half == 1) red2[j] = sum;
    __syncthreads();

    __shared__ float red[128];
    float mean = 0.f;
    if (half == 0) {
        float total = sum + red2[j];
        if (j < NCOLS) {
            mean = cnt ? total / (float)cnt : 0.f;
            g_sampled[i * NCOLS + j] = mean;
        }
        red[j] = mean;
    }
    __syncthreads();
    if (threadIdx.x < 64)  red[threadIdx.x] += red[threadIdx.x + 64];
    __syncthreads();
    if (threadIdx.x < 32) {
        float r = red[threadIdx.x] + red[threadIdx.x + 32];
        #pragma unroll
        for (int off = 16; off; off >>= 1)
            r += __shfl_xor_sync(0xffffffffu, r, off);
        if (threadIdx.x == 0) g_rowflag[i] = (r != 0.f);
    }
}

// ---- kernel 4: row compaction into d_out ----
__global__ void k_compact(float* __restrict__ out, int out_size) {
    __shared__ int sflag[NLEN];
    __shared__ int ssrc[NLEN];
    int tid = threadIdx.x;   // 512 threads
    int f = g_rowflag[tid];
    sflag[tid] = f;
    __syncthreads();
    for (int off = 1; off < NLEN; off <<= 1) {
        int v = (tid >= off) ? sflag[tid - off] : 0;
        __syncthreads();
        sflag[tid] += v;
        __syncthreads();
    }
    if (f) ssrc[sflag[tid] - 1] = tid;
    __syncthreads();
    int R = sflag[NLEN - 1];
    int total = R * NCOLS;
    if (total > out_size) total = out_size;
    for (int k = tid; k < total; k += NLEN) {
        int r = k / NCOLS;
        int c = k - r * NCOLS;
        out[k] = g_sampled[ssrc[r] * NCOLS + c];
    }
}

extern "C" void kernel_launch(void* const* d_in, const int* in_sizes, int n_in,
                              void* d_out, int out_size) {
    const float* frames   = (const float*)d_in[0];
    const int*   lips_idx = (const int*)d_in[1];
    float*       out      = (float*)d_out;

    k_init<<<1, 128>>>();
    k_frame<<<T_FRAMES / FPB, FPB * 32>>>(frames, lips_idx);
    k_scan<<<1, 1024>>>();
    k_segment<<<NLEN, 256>>>();
    k_compact<<<1, NLEN>>>(out, out_size);
}

// round 3
// speedup vs baseline: 2.0612x; 1.4830x over previous
#include <cuda_runtime.h>

#define T_FRAMES 32768
#define N_LM 543
#define NLEN 512
#define NCOLS 122   // 21*2 hand + 40*2 lips
#define NHANDF 42
#define NLIPSF 80
#define FPB 8       // frames per block in k_frame (256 threads)
#define RAWS 128    // padded row stride of g_raw (floats) -> 512B aligned rows
#define NBLK (T_FRAMES / FPB)

// ---- device scratch (static; no allocations) ----
__device__ __align__(128) float g_raw[T_FRAMES * RAWS];
__device__ __align__(128) unsigned char g_keep8[NBLK];   // 1 bit per frame
__device__ __align__(128) int   g_map[T_FRAMES];
__device__ float g_lsum[NLIPSF];
__device__ int   g_lcnt[NLIPSF];
__device__ float g_lmean[NLIPSF];
__device__ int   g_S;
__device__ __align__(128) float g_sampled[NLEN * NCOLS];
__device__ int   g_rowflag[NLEN];

__device__ __forceinline__ bool is_nan(float v) { return v != v; }

// ---- kernel 0: zero accumulators (must run every replay) ----
__global__ void k_init() {
    int i = threadIdx.x;
    if (i < NLIPSF) { g_lsum[i] = 0.f; g_lcnt[i] = 0; }
}

// ---- kernel 1: per-frame hand transform + keep bit + raw buffer + lips accum ----
__global__ void k_frame(const float* __restrict__ frames, const int* __restrict__ lips_idx) {
    __shared__ int   s_lidx[40];
    __shared__ float s_lips[FPB][NLIPSF];
    __shared__ int   s_keepw[FPB];

    int tib  = threadIdx.x;
    int lane = tib & 31;
    int w    = tib >> 5;
    int t    = blockIdx.x * FPB + w;
    const float NANF = __int_as_float(0x7fc00000);

    if (tib < 40) s_lidx[tib] = lips_idx[tib];
    __syncthreads();

    const float* fb = frames + (size_t)t * (N_LM * 3);

    int nz = 0;
    if (lane < 21) {
        float lx = __ldg(&fb[(468 + lane) * 3 + 0]);
        float ly = __ldg(&fb[(468 + lane) * 3 + 1]);
        float rx = __ldg(&fb[(522 + lane) * 3 + 0]);
        float ry = __ldg(&fb[(522 + lane) * 3 + 1]);
        float a0 = is_nan(lx) ? 0.f : lx;
        float a1 = is_nan(ly) ? 0.f : (1.f - ly);
        float b0 = is_nan(rx) ? 0.f : (1.f - rx);
        float b1 = is_nan(ry) ? 0.f : (1.f - ry);
        float h0 = a0 + b0;
        float h1 = a1 + b1;
        g_raw[t * RAWS + 2 * lane + 0] = h0;
        g_raw[t * RAWS + 2 * lane + 1] = h1;
        nz = (h0 != 0.f) | (h1 != 0.f);   // terms are non-negative => sum!=0 <=> any!=0
    }
    unsigned bal = __ballot_sync(0xffffffffu, nz);
    int keep = (bal != 0u);
    if (lane == 0) s_keepw[w] = keep;

    // lips gather; stash (value-if-kept-else-NaN) in shared for block reduction
    #pragma unroll
    for (int j = lane; j < 40; j += 32) {
        int li  = s_lidx[j];
        float x = __ldg(&fb[li * 3 + 0]);
        float y = __ldg(&fb[li * 3 + 1]);
        g_raw[t * RAWS + NHANDF + 2 * j + 0] = x;
        g_raw[t * RAWS + NHANDF + 2 * j + 1] = y;
        s_lips[w][2 * j + 0] = keep ? x : NANF;
        s_lips[w][2 * j + 1] = keep ? y : NANF;
    }
    __syncthreads();

    if (tib == 0) {
        unsigned m = 0;
        #pragma unroll
        for (int f = 0; f < FPB; f++) m |= (unsigned)s_keepw[f] << f;
        g_keep8[blockIdx.x] = (unsigned char)m;
    }

    // 80 threads: reduce FPB frames for one column, single global atomic pair
    if (tib < NLIPSF) {
        float s = 0.f; int c = 0;
        #pragma unroll
        for (int f = 0; f < FPB; f++) {
            float v = s_lips[f][tib];
            if (!is_nan(v)) { s += v; c++; }
        }
        if (c) {
            atomicAdd(&g_lsum[tib], s);
            atomicAdd(&g_lcnt[tib], c);
        }
    }
}

// ---- kernel 2: ballot-based compaction of keep bits -> g_map + S; lips means ----
__global__ void k_scan() {
    int tid  = threadIdx.x;   // 1024 threads = 32 warps
    int lane = tid & 31;
    int w    = tid >> 5;

    if (tid < NLIPSF) {
        int c = g_lcnt[tid];
        g_lmean[tid] = (c > 0) ? g_lsum[tid] / (float)c : 0.f;
    }

    __shared__ unsigned s_ball[1024];  // [warp][k]
    __shared__ int s_cnt[32];
    __shared__ int s_off[32];

    int t0  = w * 1024;
    int cnt = 0;
    #pragma unroll
    for (int k = 0; k < 32; k++) {
        int t  = t0 + k * 32 + lane;
        int kp = (g_keep8[t >> 3] >> (t & 7)) & 1;
        unsigned b = __ballot_sync(0xffffffffu, kp);
        if (lane == 0) s_ball[w * 32 + k] = b;
        cnt += __popc(b);
    }
    if (lane == 0) s_cnt[w] = cnt;
    __syncthreads();
    if (tid == 0) {
        int acc = 0;
        #pragma unroll
        for (int i = 0; i < 32; i++) { s_off[i] = acc; acc += s_cnt[i]; }
        g_S = acc;
    }
    __syncthreads();

    int off = s_off[w];
    #pragma unroll
    for (int k = 0; k < 32; k++) {
        unsigned b = s_ball[w * 32 + k];
        int t = t0 + k * 32 + lane;
        if ((b >> lane) & 1)
            g_map[off + __popc(b & ((1u << lane) - 1u))] = t;
        off += __popc(b);
    }
}

// ---- kernel 3: segment means (512 blocks x 512 thr = 128 cols x 4 slices) ----
__global__ void k_segment() {
    int i = blockIdx.x;
    int S = g_S;
    int lo = 0, hi = 0;
    if (S >= 2) {
        long sm1 = (long)(S - 1);
        lo = (int)(((long)i       * sm1) >> 9);   // floor(i*(S-1)/512)
        hi = (int)(((long)(i + 1) * sm1) >> 9);
    }
    int cnt = hi - lo;   // <= 64

    __shared__ int   s_map[66];
    __shared__ float red[4][128];

    if (threadIdx.x < cnt) s_map[threadIdx.x] = g_map[lo + threadIdx.x];
    __syncthreads();

    int j     = threadIdx.x & 127;
    int slice = threadIdx.x >> 7;

    float sum = 0.f;
    if (j < NCOLS) {
        float fill = (j >= NHANDF) ? g_lmean[j - NHANDF] : 0.f;
        #pragma unroll 2
        for (int s = slice; s < cnt; s += 4) {
            int t = s_map[s];
            float v = g_raw[t * RAWS + j];
            sum += is_nan(v) ? fill : v;
        }
    }
    red[slice][j] = sum;
    __syncthreads();

    float mean = 0.f;
    if (slice == 0) {
        float total = red[0][j] + red[1][j] + red[2][j] + red[3][j];
        if (j < NCOLS) {
            mean = cnt ? total / (float)cnt : 0.f;
            g_sampled[i * NCOLS + j] = mean;
        }
    }
    __syncthreads();
    if (slice == 0) red[0][j] = mean;
    __syncthreads();
    if (threadIdx.x < 32) {
        float r = red[0][threadIdx.x] + red[0][threadIdx.x + 32]
                + red[0][threadIdx.x + 64] + red[0][threadIdx.x + 96];
        #pragma unroll
        for (int off = 16; off; off >>= 1)
            r += __shfl_xor_sync(0xffffffffu, r, off);
        if (threadIdx.x == 0) g_rowflag[i] = (r != 0.f);
    }
}

// ---- kernel 4: row compaction into d_out ----
__global__ void k_compact(float* __restrict__ out, int out_size) {
    __shared__ int sflag[NLEN];
    __shared__ int ssrc[NLEN];
    int tid = threadIdx.x;   // 512 threads
    int f = g_rowflag[tid];
    sflag[tid] = f;
    __syncthreads();
    for (int off = 1; off < NLEN; off <<= 1) {
        int v = (tid >= off) ? sflag[tid - off] : 0;
        __syncthreads();
        sflag[tid] += v;
        __syncthreads();
    }
    if (f) ssrc[sflag[tid] - 1] = tid;
    __syncthreads();
    int R = sflag[NLEN - 1];
    int total = R * NCOLS;
    if (total > out_size) total = out_size;
    for (int k = tid; k < total; k += NLEN) {
        int r = k / NCOLS;
        int c = k - r * NCOLS;
        out[k] = g_sampled[ssrc[r] * NCOLS + c];
    }
}

extern "C" void kernel_launch(void* const* d_in, const int* in_sizes, int n_in,
                              void* d_out, int out_size) {
    const float* frames   = (const float*)d_in[0];
    const int*   lips_idx = (const int*)d_in[1];
    float*       out      = (float*)d_out;

    k_init<<<1, 128>>>();
    k_frame<<<NBLK, FPB * 32>>>(frames, lips_idx);
    k_scan<<<1, 1024>>>();
    k_segment<<<NLEN, 512>>>();
    k_compact<<<1, NLEN>>>(out, out_size);
}